// round 11
// baseline (speedup 1.0000x reference)
#include <cuda_runtime.h>
#include <cuda_fp16.h>
#include <cstdint>
#include <cstring>

#define T_STEPS 20
#define N_NODES 50000
#define K_ACT   10000
#define RNN     128
#define OUT_SZ  5
#define M_TILES 79
#define MG_CNT  (M_TILES * 8)     // 632 groups of 16 rows
#define K16     16                // 256 / 16

// -------- device scratch (static; no allocation) --------
// A in m16n8k16 fp16 fragment layout: [mg][k16][lane] -> uint4 (regs a0..a3)
__device__ uint4 g_Afrag[(size_t)MG_CNT * K16 * 32];
// B in k16n8 fp16 fragment layout: [nf][k16][lane] -> uint2 (regs b0,b1)
__device__ uint2 g_Bfrag[64 * K16 * 32];
__device__ float4 g_br[RNN];                   // per-unit (bi,bf,bg,bo)
__device__ float  g_cg[(size_t)K_ACT * RNN];   // dense c gather per frame
__device__ float  g_hs[(size_t)K_ACT * RNN];   // h_new scratch
__device__ float  g_cs[(size_t)K_ACT * RNN];   // c_new scratch
__device__ int    g_winner[N_NODES];           // last-wins stamps

// ======================= helpers =======================
__device__ __forceinline__ float sigf(float x)   { return __fdividef(1.f, 1.f + __expf(-x)); }
__device__ __forceinline__ float tanhfa(float x) { return __fdividef(2.f, 1.f + __expf(-2.f * x)) - 1.f; }

__device__ __forceinline__ uint32_t h2u(__half2 v) {
    uint32_t u;
    memcpy(&u, &v, 4);
    return u;
}
__device__ __forceinline__ uint32_t smem_u32(const void* p) {
    uint32_t a;
    asm("{ .reg .u64 t; cvta.to.shared.u64 t, %1; cvt.u32.u64 %0, t; }" : "=r"(a) : "l"(p));
    return a;
}
#define CPA16(s, g) asm volatile("cp.async.cg.shared.global [%0], [%1], 16;" :: "r"(s), "l"(g))

// Write an even-aligned (col j, j+1) half2 pair of A in fragment layout.
__device__ __forceinline__ void writeA2(int m, int j, __half2 v) {
    int mg = m >> 4, r = m & 15;
    int k16 = j >> 4, kk = j & 15;                 // kk even
    int lane = (r & 7) * 4 + ((kk & 7) >> 1);
    int reg  = ((kk >> 3) << 1) | (r >> 3);
    ((uint32_t*)g_Afrag)[((((size_t)mg * K16 + k16) * 32) + lane) * 4 + reg] = h2u(v);
}

#define MMA_F16(cc, aa, bb) \
    asm volatile("mma.sync.aligned.m16n8k16.row.col.f32.f16.f16.f32 " \
        "{%0,%1,%2,%3},{%4,%5,%6,%7},{%8,%9},{%0,%1,%2,%3};" \
        : "+f"((cc)[0]), "+f"((cc)[1]), "+f"((cc)[2]), "+f"((cc)[3]) \
        : "r"((aa).x), "r"((aa).y), "r"((aa).z), "r"((aa).w), \
          "r"((bb).x), "r"((bb).y))

// ======================= init kernels =======================
__global__ void init_weights_kernel(const float* __restrict__ W_ih, const float* __restrict__ b_ih,
                                    const float* __restrict__ W_hh, const float* __restrict__ b_hh)
{
    int cp = blockIdx.x;     // rearranged column col' = unit*4+gate, 0..511
    int r  = threadIdx.x;    // inner k, 0..255
    int unit = cp >> 2, gate = cp & 3;
    int col = gate * RNN + unit;
    float v = (r < RNN) ? W_ih[r * 512 + col] : W_hh[(r - RNN) * 512 + col];
    int nf = cp >> 3;
    int lane = (cp & 7) * 4 + ((r & 7) >> 1);
    int reg = (r >> 3) & 1, halfpos = r & 1, k16 = r >> 4;
    ((__half*)g_Bfrag)[((((size_t)nf * K16 + k16) * 32 + lane) * 2 + reg) * 2 + halfpos] = __float2half_rn(v);
    if (r == 0) ((float*)g_br)[cp] = b_ih[col] + b_hh[col];
}

__global__ void init_state_kernel(float* __restrict__ out,
                                  const float* __restrict__ h0, const float* __restrict__ c0)
{
    const int OUT_TOTAL = T_STEPS * N_NODES * OUT_SZ;
    const int HOFF = OUT_TOTAL;
    const int COFF = HOFF + N_NODES * RNN;
    const int WOFF = COFF + N_NODES * RNN;
    const int TOTAL = WOFF + N_NODES;
    for (int i = blockIdx.x * blockDim.x + threadIdx.x; i < TOTAL; i += gridDim.x * blockDim.x) {
        if (i < OUT_TOTAL)      out[i] = 0.f;
        else if (i < COFF)      out[i] = h0[i - HOFF];
        else if (i < WOFF)      out[i] = c0[i - COFF];
        else                    g_winner[i - WOFF] = -1;
    }
}

// ======================= per-frame: embed + gather + stamp =======================
__global__ __launch_bounds__(256) void embed_kernel(
    const float* __restrict__ input_data, const float* __restrict__ grids,
    const int* __restrict__ active_idx,
    const float* __restrict__ W_in, const float* __restrict__ b_in,
    const float* __restrict__ W_obs, const float* __restrict__ b_obs,
    const float* __restrict__ h_all, const float* __restrict__ c_all, int t)
{
    int wid = threadIdx.x >> 5, lane = threadIdx.x & 31;
    int k = blockIdx.x * 8 + wid;
    if (k >= K_ACT) return;
    int n = active_idx[t * K_ACT + k];
    if (lane == 0) atomicMax(&g_winner[n], t * K_ACT + k);

    // h gather -> A cols 128..255 (fp16); c gather -> dense scratch
    float4 h4 = *(const float4*)&h_all[(size_t)n * RNN + lane * 4];
    int jh = 128 + lane * 4;
    writeA2(k, jh + 0, __floats2half2_rn(h4.x, h4.y));
    writeA2(k, jh + 2, __floats2half2_rn(h4.z, h4.w));
    float4 c4 = *(const float4*)&c_all[(size_t)n * RNN + lane * 4];
    *(float4*)&g_cg[(size_t)k * RNN + lane * 4] = c4;

    // input embedding -> A cols 0..63 (this thread: cols 2*lane, 2*lane+1)
    float x0 = input_data[((size_t)t * N_NODES + n) * 2 + 0];
    float x1 = input_data[((size_t)t * N_NODES + n) * 2 + 1];
    {
        int j = 2 * lane;
        float v0 = fmaf(x0, W_in[j],     fmaf(x1, W_in[64 + j],     b_in[j]));
        float v1 = fmaf(x0, W_in[j + 1], fmaf(x1, W_in[64 + j + 1], b_in[j + 1]));
        writeA2(k, j, __floats2half2_rn(fmaxf(v0, 0.f), fmaxf(v1, 0.f)));
    }
    // grid embedding -> A cols 64..127 (this thread: cols 64+2*lane, +1)
    const float* gp = grids + ((size_t)t * K_ACT + k) * 16;
    float obs[16];
    #pragma unroll
    for (int g = 0; g < 16; g++) obs[g] = gp[g];
    {
        int j = 2 * lane;
        float a0 = b_obs[j], a1 = b_obs[j + 1];
        #pragma unroll
        for (int g = 0; g < 16; g++) {
            a0 = fmaf(obs[g], W_obs[g * 64 + j],     a0);
            a1 = fmaf(obs[g], W_obs[g * 64 + j + 1], a1);
        }
        writeA2(k, 64 + j, __floats2half2_rn(fmaxf(a0, 0.f), fmaxf(a1, 0.f)));
    }
}

// ======================= per-frame: smem-pipelined fp16 GEMM + LSTM epilogue =======================
// grid (79, 4), 256 threads, 128KB dyn smem (1 CTA/SM). Block tile 128m x 128n.
// K = 256 in 4 chunks of 64 (4 k16-steps each); 4 cp.async commit-groups issued up
// front, chunk c computed after wait_group(3-c) -> load/compute overlap. Mainloop
// operands come from LDS (29cyc) instead of LDG/L2 (234cyc).
__global__ __launch_bounds__(256) void gemm_kernel()
{
    extern __shared__ char sm[];
    uint4* sA = (uint4*)sm;                 // [8 mg][16 k16][32 lane] : 64KB
    uint2* sB = (uint2*)(sm + 65536);       // [16 nf][16 k16][32 lane] : 64KB

    const int tid = threadIdx.x, wid = tid >> 5, lane = tid & 31;
    const int wm = wid & 3, wn = wid >> 2;
    const int bx = blockIdx.x, ny = blockIdx.y;
    const int g = lane >> 2, tg = lane & 3;

    // ---- issue 4 chunk copy groups (A 16KB + B 16KB each) ----
    {
        const uint4* gA = g_Afrag + (size_t)bx * 8 * K16 * 32;
        const char*  gB = (const char*)(g_Bfrag + (size_t)ny * 16 * K16 * 32);
        uint32_t sa = smem_u32(sA), sb = smem_u32(sB);
        #pragma unroll
        for (int c = 0; c < 4; c++) {
            #pragma unroll
            for (int i = 0; i < 4; i++) {           // A: 1024 16B units per chunk
                int idx = tid + i * 256;
                int mg = idx >> 7, rem = idx & 127;
                int kk = rem >> 5, ln = rem & 31;
                uint32_t off = (uint32_t)(((mg * K16 + c * 4 + kk) * 32 + ln) * 16);
                CPA16(sa + off, gA + (off >> 4));
            }
            #pragma unroll
            for (int i = 0; i < 4; i++) {           // B: 1024 16B units per chunk
                int idx = tid + i * 256;
                int nf = idx >> 6, rem = idx & 63;
                int kk = rem >> 4, u = rem & 15;
                uint32_t off = (uint32_t)(((nf * K16 + c * 4 + kk) * 32) * 8 + u * 16);
                CPA16(sb + off, gB + off);
            }
            asm volatile("cp.async.commit_group;" ::: "memory");
        }
    }

    float c[2][8][4];
    #pragma unroll
    for (int f = 0; f < 2; f++)
        #pragma unroll
        for (int j = 0; j < 8; j++)
            { c[f][j][0] = 0.f; c[f][j][1] = 0.f; c[f][j][2] = 0.f; c[f][j][3] = 0.f; }

    const uint4* A0 = sA + (wm * 2 + 0) * K16 * 32 + lane;
    const uint4* A1 = sA + (wm * 2 + 1) * K16 * 32 + lane;
    const uint2* Bq = sB + (wn * 8) * K16 * 32 + lane;

    #pragma unroll
    for (int ch = 0; ch < 4; ch++) {
        switch (ch) {   // wait until groups 0..ch have landed
            case 0: asm volatile("cp.async.wait_group 3;" ::: "memory"); break;
            case 1: asm volatile("cp.async.wait_group 2;" ::: "memory"); break;
            case 2: asm volatile("cp.async.wait_group 1;" ::: "memory"); break;
            case 3: asm volatile("cp.async.wait_group 0;" ::: "memory"); break;
        }
        __syncthreads();
        #pragma unroll
        for (int kk = 0; kk < 4; kk++) {
            int k16 = ch * 4 + kk;
            uint4 a0 = A0[k16 * 32];
            uint4 a1 = A1[k16 * 32];
            uint2 bf[8];
            #pragma unroll
            for (int j = 0; j < 8; j++) bf[j] = Bq[(j * K16 + k16) * 32];
            #pragma unroll
            for (int j = 0; j < 8; j++) {
                MMA_F16(c[0][j], a0, bf[j]);
                MMA_F16(c[1][j], a1, bf[j]);
            }
        }
    }

    // ---- LSTM epilogue (C layout identical to previous rounds) ----
    #pragma unroll
    for (int f = 0; f < 2; f++) {
        #pragma unroll
        for (int j = 0; j < 8; j++) {
            float x0 = __shfl_xor_sync(0xffffffffu, c[f][j][0], 1);
            float x1 = __shfl_xor_sync(0xffffffffu, c[f][j][1], 1);
            float x2 = __shfl_xor_sync(0xffffffffu, c[f][j][2], 1);
            float x3 = __shfl_xor_sync(0xffffffffu, c[f][j][3], 1);
            int odd = lane & 1;
            float gi = odd ? x2 : c[f][j][0];
            float gf = odd ? x3 : c[f][j][1];
            float gg = odd ? c[f][j][2] : x0;
            float go = odd ? c[f][j][3] : x1;
            int row = bx * 128 + wm * 32 + f * 16 + g + odd * 8;
            if (row < K_ACT) {
                int u = (ny * 16 + wn * 8 + j) * 2 + (tg >> 1);
                float4 br = g_br[u];
                float co = g_cg[(size_t)row * RNN + u];
                float ii = sigf(gi + br.x);
                float ff = sigf(gf + br.y);
                float G  = tanhfa(gg + br.z);
                float oo = sigf(go + br.w);
                float cn = fmaf(ff, co, ii * G);
                float hn = oo * tanhfa(cn);
                g_hs[(size_t)row * RNN + u] = hn;
                g_cs[(size_t)row * RNN + u] = cn;
            }
        }
    }
}

// ======================= per-frame: winner scatter + output projection =======================
__global__ __launch_bounds__(256) void scatter_kernel(
    const int* __restrict__ active_idx,
    const float* __restrict__ W_out, const float* __restrict__ b_out,
    float* __restrict__ outputs, float* __restrict__ h_all, float* __restrict__ c_all, int t)
{
    int lane = threadIdx.x & 31;
    int k = blockIdx.x * 8 + (threadIdx.x >> 5);
    if (k >= K_ACT) return;
    int n = active_idx[t * K_ACT + k];
    if (g_winner[n] != t * K_ACT + k) return;   // last-occurrence wins

    float4 h4 = *(float4*)&g_hs[(size_t)k * RNN + lane * 4];
    float4 c4 = *(float4*)&g_cs[(size_t)k * RNN + lane * 4];
    *(float4*)&h_all[(size_t)n * RNN + lane * 4] = h4;
    *(float4*)&c_all[(size_t)n * RNN + lane * 4] = c4;

    float p[OUT_SZ];
    int i0 = lane * 4;
    #pragma unroll
    for (int j = 0; j < OUT_SZ; j++) {
        p[j] = h4.x * W_out[(i0 + 0) * OUT_SZ + j]
             + h4.y * W_out[(i0 + 1) * OUT_SZ + j]
             + h4.z * W_out[(i0 + 2) * OUT_SZ + j]
             + h4.w * W_out[(i0 + 3) * OUT_SZ + j];
    }
    #pragma unroll
    for (int off = 16; off > 0; off >>= 1) {
        #pragma unroll
        for (int j = 0; j < OUT_SZ; j++)
            p[j] += __shfl_down_sync(0xffffffffu, p[j], off);
    }
    if (lane == 0) {
        #pragma unroll
        for (int j = 0; j < OUT_SZ; j++)
            outputs[((size_t)t * N_NODES + n) * OUT_SZ + j] = p[j] + b_out[j];
    }
}

// ======================= launcher =======================
extern "C" void kernel_launch(void* const* d_in, const int* in_sizes, int n_in,
                              void* d_out, int out_size)
{
    const float* input_data = (const float*)d_in[0];
    const float* grids      = (const float*)d_in[1];
    const float* h0         = (const float*)d_in[2];
    const float* c0         = (const float*)d_in[3];
    const int*   active_idx = (const int*)  d_in[4];
    const float* W_in       = (const float*)d_in[5];
    const float* b_in       = (const float*)d_in[6];
    const float* W_obs      = (const float*)d_in[7];
    const float* b_obs      = (const float*)d_in[8];
    const float* W_ih       = (const float*)d_in[9];
    const float* b_ih       = (const float*)d_in[10];
    const float* W_hh       = (const float*)d_in[11];
    const float* b_hh       = (const float*)d_in[12];
    const float* W_out      = (const float*)d_in[13];
    const float* b_out      = (const float*)d_in[14];

    float* out     = (float*)d_out;
    float* outputs = out;
    float* h_all   = out + (size_t)T_STEPS * N_NODES * OUT_SZ;
    float* c_all   = h_all + (size_t)N_NODES * RNN;

    const int SMEM = 131072;
    cudaFuncSetAttribute(gemm_kernel, cudaFuncAttributeMaxDynamicSharedMemorySize, SMEM);

    init_weights_kernel<<<512, 256>>>(W_ih, b_ih, W_hh, b_hh);
    init_state_kernel<<<1024, 256>>>(out, h0, c0);

    for (int t = 0; t < T_STEPS; t++) {
        embed_kernel<<<(K_ACT + 7) / 8, 256>>>(input_data, grids, active_idx,
                                               W_in, b_in, W_obs, b_obs, h_all, c_all, t);
        gemm_kernel<<<dim3(M_TILES, 4), 256, SMEM>>>();
        scatter_kernel<<<(K_ACT + 7) / 8, 256>>>(active_idx, W_out, b_out,
                                                 outputs, h_all, c_all, t);
    }
}

// round 13
// speedup vs baseline: 1.0398x; 1.0398x over previous
#include <cuda_runtime.h>
#include <cuda_fp16.h>
#include <cstdint>
#include <cstring>

#define T_STEPS 20
#define N_NODES 50000
#define K_ACT   10000
#define RNN     128
#define OUT_SZ  5
#define M_TILES 79
#define MG_CNT  (M_TILES * 8)     // 632 groups of 16 rows
#define K16     16                // 256 / 16

// -------- device scratch (static; no allocation) --------
// A in m16n8k16 fp16 fragment layout: [mg][k16][lane] -> uint4 (regs a0..a3)
__device__ uint4 g_Afrag[(size_t)MG_CNT * K16 * 32];
// B in k16n8 fp16 fragment layout: [nf][k16][lane] -> uint2 (regs b0,b1)
__device__ uint2 g_Bfrag[64 * K16 * 32];
__device__ float4 g_br[RNN];                   // per-unit (bi,bf,bg,bo)
__device__ float  g_cg[(size_t)K_ACT * RNN];   // dense c gather per frame
__device__ float  g_hs[(size_t)K_ACT * RNN];   // h_new scratch
__device__ float  g_cs[(size_t)K_ACT * RNN];   // c_new scratch
__device__ int    g_winner[N_NODES];           // last-wins stamps

// ======================= helpers =======================
__device__ __forceinline__ float sigf(float x)   { return __fdividef(1.f, 1.f + __expf(-x)); }
__device__ __forceinline__ float tanhfa(float x) { return __fdividef(2.f, 1.f + __expf(-2.f * x)) - 1.f; }

__device__ __forceinline__ uint32_t h2u(__half2 v) {
    uint32_t u;
    memcpy(&u, &v, 4);
    return u;
}
__device__ __forceinline__ uint32_t smem_u32(const void* p) {
    uint32_t a;
    asm("{ .reg .u64 t; cvta.to.shared.u64 t, %1; cvt.u32.u64 %0, t; }" : "=r"(a) : "l"(p));
    return a;
}
#define CPA16(s, g) asm volatile("cp.async.cg.shared.global [%0], [%1], 16;" :: "r"(s), "l"(g))

// Write an even-aligned (col j, j+1) half2 pair of A in fragment layout.
__device__ __forceinline__ void writeA2(int m, int j, __half2 v) {
    int mg = m >> 4, r = m & 15;
    int k16 = j >> 4, kk = j & 15;                 // kk even
    int lane = (r & 7) * 4 + ((kk & 7) >> 1);
    int reg  = ((kk >> 3) << 1) | (r >> 3);
    ((uint32_t*)g_Afrag)[((((size_t)mg * K16 + k16) * 32) + lane) * 4 + reg] = h2u(v);
}

#define MMA_F16(cc, aa, bb) \
    asm volatile("mma.sync.aligned.m16n8k16.row.col.f32.f16.f16.f32 " \
        "{%0,%1,%2,%3},{%4,%5,%6,%7},{%8,%9},{%0,%1,%2,%3};" \
        : "+f"((cc)[0]), "+f"((cc)[1]), "+f"((cc)[2]), "+f"((cc)[3]) \
        : "r"((aa).x), "r"((aa).y), "r"((aa).z), "r"((aa).w), \
          "r"((bb).x), "r"((bb).y))

// ======================= init kernels =======================
__global__ void init_weights_kernel(const float* __restrict__ W_ih, const float* __restrict__ b_ih,
                                    const float* __restrict__ W_hh, const float* __restrict__ b_hh)
{
    int cp = blockIdx.x;     // rearranged column col' = unit*4+gate, 0..511
    int r  = threadIdx.x;    // inner k, 0..255
    int unit = cp >> 2, gate = cp & 3;
    int col = gate * RNN + unit;
    float v = (r < RNN) ? W_ih[r * 512 + col] : W_hh[(r - RNN) * 512 + col];
    int nf = cp >> 3;
    int lane = (cp & 7) * 4 + ((r & 7) >> 1);
    int reg = (r >> 3) & 1, halfpos = r & 1, k16 = r >> 4;
    ((__half*)g_Bfrag)[((((size_t)nf * K16 + k16) * 32 + lane) * 2 + reg) * 2 + halfpos] = __float2half_rn(v);
    if (r == 0) ((float*)g_br)[cp] = b_ih[col] + b_hh[col];
}

__global__ void init_state_kernel(float* __restrict__ out,
                                  const float* __restrict__ h0, const float* __restrict__ c0)
{
    const int OUT_TOTAL = T_STEPS * N_NODES * OUT_SZ;
    const int HOFF = OUT_TOTAL;
    const int COFF = HOFF + N_NODES * RNN;
    const int WOFF = COFF + N_NODES * RNN;
    const int TOTAL = WOFF + N_NODES;
    for (int i = blockIdx.x * blockDim.x + threadIdx.x; i < TOTAL; i += gridDim.x * blockDim.x) {
        if (i < OUT_TOTAL)      out[i] = 0.f;
        else if (i < COFF)      out[i] = h0[i - HOFF];
        else if (i < WOFF)      out[i] = c0[i - COFF];
        else                    g_winner[i - WOFF] = -1;
    }
}

// ======================= per-frame: embed + gather + stamp =======================
__global__ __launch_bounds__(256) void embed_kernel(
    const float* __restrict__ input_data, const float* __restrict__ grids,
    const int* __restrict__ active_idx,
    const float* __restrict__ W_in, const float* __restrict__ b_in,
    const float* __restrict__ W_obs, const float* __restrict__ b_obs,
    const float* __restrict__ h_all, const float* __restrict__ c_all, int t)
{
    int wid = threadIdx.x >> 5, lane = threadIdx.x & 31;
    int k = blockIdx.x * 8 + wid;
    if (k >= K_ACT) return;
    int n = active_idx[t * K_ACT + k];
    if (lane == 0) atomicMax(&g_winner[n], t * K_ACT + k);

    // h gather -> A cols 128..255 (fp16); c gather -> dense scratch
    float4 h4 = *(const float4*)&h_all[(size_t)n * RNN + lane * 4];
    int jh = 128 + lane * 4;
    writeA2(k, jh + 0, __floats2half2_rn(h4.x, h4.y));
    writeA2(k, jh + 2, __floats2half2_rn(h4.z, h4.w));
    float4 c4 = *(const float4*)&c_all[(size_t)n * RNN + lane * 4];
    *(float4*)&g_cg[(size_t)k * RNN + lane * 4] = c4;

    // input embedding -> A cols 0..63 (this thread: cols 2*lane, 2*lane+1)
    float x0 = input_data[((size_t)t * N_NODES + n) * 2 + 0];
    float x1 = input_data[((size_t)t * N_NODES + n) * 2 + 1];
    {
        int j = 2 * lane;
        float v0 = fmaf(x0, W_in[j],     fmaf(x1, W_in[64 + j],     b_in[j]));
        float v1 = fmaf(x0, W_in[j + 1], fmaf(x1, W_in[64 + j + 1], b_in[j + 1]));
        writeA2(k, j, __floats2half2_rn(fmaxf(v0, 0.f), fmaxf(v1, 0.f)));
    }
    // grid embedding -> A cols 64..127 (this thread: cols 64+2*lane, +1)
    const float* gp = grids + ((size_t)t * K_ACT + k) * 16;
    float obs[16];
    #pragma unroll
    for (int g = 0; g < 16; g++) obs[g] = gp[g];
    {
        int j = 2 * lane;
        float a0 = b_obs[j], a1 = b_obs[j + 1];
        #pragma unroll
        for (int g = 0; g < 16; g++) {
            a0 = fmaf(obs[g], W_obs[g * 64 + j],     a0);
            a1 = fmaf(obs[g], W_obs[g * 64 + j + 1], a1);
        }
        writeA2(k, 64 + j, __floats2half2_rn(fmaxf(a0, 0.f), fmaxf(a1, 0.f)));
    }
}

// ======================= per-frame: double-buffered smem fp16 GEMM + LSTM epilogue =======================
// grid (79, 4), 256 threads, 64KB dyn smem -> 2 CTAs/SM (16 warps). Block tile 128m x 128n.
// K = 256 in 4 chunks of 64; 2-stage cp.async double buffer: compute chunk c from stage c&1
// while chunk c+1 is in flight; stage freed by a barrier then refilled with chunk c+2.
#define STAGE_BYTES 32768     // A 16KB + B 16KB

// Copy chunk ch (k16 in [4ch,4ch+4)) of this CTA's A/B slices into stage (sa, sb).
__device__ __forceinline__ void load_chunk(uint32_t sa, uint32_t sb, int bx, int ny, int ch, int tid)
{
    const char* gA = (const char*)(g_Afrag + (size_t)bx * 8 * K16 * 32);
    const char* gB = (const char*)(g_Bfrag + (size_t)ny * 16 * K16 * 32);
    #pragma unroll
    for (int i = 0; i < 4; i++) {           // A: 1024 16B units
        int idx = tid + i * 256;
        int mg = idx >> 7, rem = idx & 127;
        int kk = rem >> 5, ln = rem & 31;
        uint32_t dst = sa + (uint32_t)(((mg * 4 + kk) * 32 + ln) * 16);
        uint32_t src = (uint32_t)(((mg * K16 + ch * 4 + kk) * 32 + ln) * 16);
        CPA16(dst, gA + src);
    }
    #pragma unroll
    for (int i = 0; i < 4; i++) {           // B: 1024 16B units
        int idx = tid + i * 256;
        int nf = idx >> 6, rem = idx & 63;
        int kk = rem >> 4, u = rem & 15;
        uint32_t dst = sb + (uint32_t)(((nf * 4 + kk) * 32) * 8 + u * 16);
        uint32_t src = (uint32_t)(((nf * K16 + ch * 4 + kk) * 32) * 8 + u * 16);
        CPA16(dst, gB + src);
    }
    asm volatile("cp.async.commit_group;" ::: "memory");
}

__global__ __launch_bounds__(256, 2) void gemm_kernel()
{
    extern __shared__ char sm[];
    const int tid = threadIdx.x, wid = tid >> 5, lane = tid & 31;
    const int wm = wid & 3, wn = wid >> 2;
    const int bx = blockIdx.x, ny = blockIdx.y;
    const int g = lane >> 2, tg = lane & 3;

    const uint32_t sbase = smem_u32(sm);

    // prologue: chunks 0,1 into stages 0,1
    load_chunk(sbase,               sbase + 16384,               bx, ny, 0, tid);
    load_chunk(sbase + STAGE_BYTES, sbase + STAGE_BYTES + 16384, bx, ny, 1, tid);

    float c[2][8][4];
    #pragma unroll
    for (int f = 0; f < 2; f++)
        #pragma unroll
        for (int j = 0; j < 8; j++)
            { c[f][j][0] = 0.f; c[f][j][1] = 0.f; c[f][j][2] = 0.f; c[f][j][3] = 0.f; }

    #pragma unroll
    for (int ch = 0; ch < 4; ch++) {
        if (ch < 3) asm volatile("cp.async.wait_group 1;" ::: "memory");
        else        asm volatile("cp.async.wait_group 0;" ::: "memory");
        __syncthreads();

        const int s = ch & 1;
        const uint4* A0 = (const uint4*)(sm + s * STAGE_BYTES) + (wm * 2 + 0) * 4 * 32 + lane;
        const uint4* A1 = (const uint4*)(sm + s * STAGE_BYTES) + (wm * 2 + 1) * 4 * 32 + lane;
        const uint2* Bq = (const uint2*)(sm + s * STAGE_BYTES + 16384) + (wn * 8) * 4 * 32 + lane;

        #pragma unroll
        for (int kk = 0; kk < 4; kk++) {
            uint4 a0 = A0[kk * 32];
            uint4 a1 = A1[kk * 32];
            uint2 bf[8];
            #pragma unroll
            for (int j = 0; j < 8; j++) bf[j] = Bq[(j * 4 + kk) * 32];
            #pragma unroll
            for (int j = 0; j < 8; j++) {
                MMA_F16(c[0][j], a0, bf[j]);
                MMA_F16(c[1][j], a1, bf[j]);
            }
        }

        if (ch < 2) {   // refill the stage just consumed with chunk ch+2
            __syncthreads();
            load_chunk(sbase + s * STAGE_BYTES, sbase + s * STAGE_BYTES + 16384, bx, ny, ch + 2, tid);
        }
    }

    // ---- LSTM epilogue (C layout identical to previous rounds) ----
    #pragma unroll
    for (int f = 0; f < 2; f++) {
        #pragma unroll
        for (int j = 0; j < 8; j++) {
            float x0 = __shfl_xor_sync(0xffffffffu, c[f][j][0], 1);
            float x1 = __shfl_xor_sync(0xffffffffu, c[f][j][1], 1);
            float x2 = __shfl_xor_sync(0xffffffffu, c[f][j][2], 1);
            float x3 = __shfl_xor_sync(0xffffffffu, c[f][j][3], 1);
            int odd = lane & 1;
            float gi = odd ? x2 : c[f][j][0];
            float gf = odd ? x3 : c[f][j][1];
            float gg = odd ? c[f][j][2] : x0;
            float go = odd ? c[f][j][3] : x1;
            int row = bx * 128 + wm * 32 + f * 16 + g + odd * 8;
            if (row < K_ACT) {
                int u = (ny * 16 + wn * 8 + j) * 2 + (tg >> 1);
                float4 br = g_br[u];
                float co = g_cg[(size_t)row * RNN + u];
                float ii = sigf(gi + br.x);
                float ff = sigf(gf + br.y);
                float G  = tanhfa(gg + br.z);
                float oo = sigf(go + br.w);
                float cn = fmaf(ff, co, ii * G);
                float hn = oo * tanhfa(cn);
                g_hs[(size_t)row * RNN + u] = hn;
                g_cs[(size_t)row * RNN + u] = cn;
            }
        }
    }
}

// ======================= per-frame: winner scatter + output projection =======================
__global__ __launch_bounds__(256) void scatter_kernel(
    const int* __restrict__ active_idx,
    const float* __restrict__ W_out, const float* __restrict__ b_out,
    float* __restrict__ outputs, float* __restrict__ h_all, float* __restrict__ c_all, int t)
{
    int lane = threadIdx.x & 31;
    int k = blockIdx.x * 8 + (threadIdx.x >> 5);
    if (k >= K_ACT) return;
    int n = active_idx[t * K_ACT + k];
    if (g_winner[n] != t * K_ACT + k) return;   // last-occurrence wins

    float4 h4 = *(float4*)&g_hs[(size_t)k * RNN + lane * 4];
    float4 c4 = *(float4*)&g_cs[(size_t)k * RNN + lane * 4];
    *(float4*)&h_all[(size_t)n * RNN + lane * 4] = h4;
    *(float4*)&c_all[(size_t)n * RNN + lane * 4] = c4;

    float p[OUT_SZ];
    int i0 = lane * 4;
    #pragma unroll
    for (int j = 0; j < OUT_SZ; j++) {
        p[j] = h4.x * W_out[(i0 + 0) * OUT_SZ + j]
             + h4.y * W_out[(i0 + 1) * OUT_SZ + j]
             + h4.z * W_out[(i0 + 2) * OUT_SZ + j]
             + h4.w * W_out[(i0 + 3) * OUT_SZ + j];
    }
    #pragma unroll
    for (int off = 16; off > 0; off >>= 1) {
        #pragma unroll
        for (int j = 0; j < OUT_SZ; j++)
            p[j] += __shfl_down_sync(0xffffffffu, p[j], off);
    }
    if (lane == 0) {
        #pragma unroll
        for (int j = 0; j < OUT_SZ; j++)
            outputs[((size_t)t * N_NODES + n) * OUT_SZ + j] = p[j] + b_out[j];
    }
}

// ======================= launcher =======================
extern "C" void kernel_launch(void* const* d_in, const int* in_sizes, int n_in,
                              void* d_out, int out_size)
{
    const float* input_data = (const float*)d_in[0];
    const float* grids      = (const float*)d_in[1];
    const float* h0         = (const float*)d_in[2];
    const float* c0         = (const float*)d_in[3];
    const int*   active_idx = (const int*)  d_in[4];
    const float* W_in       = (const float*)d_in[5];
    const float* b_in       = (const float*)d_in[6];
    const float* W_obs      = (const float*)d_in[7];
    const float* b_obs      = (const float*)d_in[8];
    const float* W_ih       = (const float*)d_in[9];
    const float* b_ih       = (const float*)d_in[10];
    const float* W_hh       = (const float*)d_in[11];
    const float* b_hh       = (const float*)d_in[12];
    const float* W_out      = (const float*)d_in[13];
    const float* b_out      = (const float*)d_in[14];

    float* out     = (float*)d_out;
    float* outputs = out;
    float* h_all   = out + (size_t)T_STEPS * N_NODES * OUT_SZ;
    float* c_all   = h_all + (size_t)N_NODES * RNN;

    const int SMEM = 2 * STAGE_BYTES;   // 64KB
    cudaFuncSetAttribute(gemm_kernel, cudaFuncAttributeMaxDynamicSharedMemorySize, SMEM);

    init_weights_kernel<<<512, 256>>>(W_ih, b_ih, W_hh, b_hh);
    init_state_kernel<<<1024, 256>>>(out, h0, c0);

    for (int t = 0; t < T_STEPS; t++) {
        embed_kernel<<<(K_ACT + 7) / 8, 256>>>(input_data, grids, active_idx,
                                               W_in, b_in, W_obs, b_obs, h_all, c_all, t);
        gemm_kernel<<<dim3(M_TILES, 4), 256, SMEM>>>();
        scatter_kernel<<<(K_ACT + 7) / 8, 256>>>(active_idx, W_out, b_out,
                                                 outputs, h_all, c_all, t);
    }
}

// round 16
// speedup vs baseline: 1.1354x; 1.0920x over previous
#include <cuda_runtime.h>
#include <cuda_fp16.h>
#include <cstdint>
#include <cstring>

#define T_STEPS 20
#define N_NODES 50000
#define K_ACT   10000
#define RNN     128
#define OUT_SZ  5
#define M_TILES 79
#define MG_CNT  (M_TILES * 8)     // 632 groups of 16 rows
#define K16     16                // 256 / 16

// -------- device scratch (static; no allocation) --------
__device__ uint4 g_Afrag[(size_t)MG_CNT * K16 * 32];   // A fp16 fragments
__device__ uint2 g_Bfrag[64 * K16 * 32];               // B fp16 fragments
__device__ float4 g_br[RNN];                   // per-unit (bi,bf,bg,bo)
__device__ float  g_cg[(size_t)K_ACT * RNN];   // dense c gather per frame
__device__ float  g_hs[(size_t)K_ACT * RNN];   // h_new scratch
__device__ float  g_cs[(size_t)K_ACT * RNN];   // c_new scratch
__device__ int    g_winner[N_NODES];           // last-wins stamps

// ======================= helpers =======================
__device__ __forceinline__ float sigf(float x)   { return __fdividef(1.f, 1.f + __expf(-x)); }
__device__ __forceinline__ float tanhfa(float x) { return __fdividef(2.f, 1.f + __expf(-2.f * x)) - 1.f; }

__device__ __forceinline__ uint32_t h2u(__half2 v) {
    uint32_t u;
    memcpy(&u, &v, 4);
    return u;
}
__device__ __forceinline__ uint32_t smem_u32(const void* p) {
    uint32_t a;
    asm("{ .reg .u64 t; cvta.to.shared.u64 t, %1; cvt.u32.u64 %0, t; }" : "=r"(a) : "l"(p));
    return a;
}
#define CPA16(s, g) asm volatile("cp.async.cg.shared.global [%0], [%1], 16;" :: "r"(s), "l"(g))

// Write an even-aligned (col j, j+1) half2 pair of A in fragment layout.
__device__ __forceinline__ void writeA2(int m, int j, __half2 v) {
    int mg = m >> 4, r = m & 15;
    int k16 = j >> 4, kk = j & 15;                 // kk even
    int lane = (r & 7) * 4 + ((kk & 7) >> 1);
    int reg  = ((kk >> 3) << 1) | (r >> 3);
    ((uint32_t*)g_Afrag)[((((size_t)mg * K16 + k16) * 32) + lane) * 4 + reg] = h2u(v);
}

#define MMA_F16(cc, aa, bb) \
    asm volatile("mma.sync.aligned.m16n8k16.row.col.f32.f16.f16.f32 " \
        "{%0,%1,%2,%3},{%4,%5,%6,%7},{%8,%9},{%0,%1,%2,%3};" \
        : "+f"((cc)[0]), "+f"((cc)[1]), "+f"((cc)[2]), "+f"((cc)[3]) \
        : "r"((aa).x), "r"((aa).y), "r"((aa).z), "r"((aa).w), \
          "r"((bb).x), "r"((bb).y))

// ======================= init kernels =======================
__global__ void init_weights_kernel(const float* __restrict__ W_ih, const float* __restrict__ b_ih,
                                    const float* __restrict__ W_hh, const float* __restrict__ b_hh)
{
    int cp = blockIdx.x;     // rearranged column col' = unit*4+gate, 0..511
    int r  = threadIdx.x;    // inner k, 0..255
    int unit = cp >> 2, gate = cp & 3;
    int col = gate * RNN + unit;
    float v = (r < RNN) ? W_ih[r * 512 + col] : W_hh[(r - RNN) * 512 + col];
    int nf = cp >> 3;
    int lane = (cp & 7) * 4 + ((r & 7) >> 1);
    int reg = (r >> 3) & 1, halfpos = r & 1, k16 = r >> 4;
    ((__half*)g_Bfrag)[((((size_t)nf * K16 + k16) * 32 + lane) * 2 + reg) * 2 + halfpos] = __float2half_rn(v);
    if (r == 0) ((float*)g_br)[cp] = b_ih[col] + b_hh[col];
}

__global__ void init_state_kernel(float* __restrict__ out,
                                  const float* __restrict__ h0, const float* __restrict__ c0)
{
    const int OUT_TOTAL = T_STEPS * N_NODES * OUT_SZ;
    const int HOFF = OUT_TOTAL;
    const int COFF = HOFF + N_NODES * RNN;
    const int WOFF = COFF + N_NODES * RNN;
    const int TOTAL = WOFF + N_NODES;
    for (int i = blockIdx.x * blockDim.x + threadIdx.x; i < TOTAL; i += gridDim.x * blockDim.x) {
        if (i < OUT_TOTAL)      out[i] = 0.f;
        else if (i < COFF)      out[i] = h0[i - HOFF];
        else if (i < WOFF)      out[i] = c0[i - COFF];
        else                    g_winner[i - WOFF] = -1;
    }
}

// ======================= per-frame: embed + gather + stamp =======================
__global__ __launch_bounds__(256) void embed_kernel(
    const float* __restrict__ input_data, const float* __restrict__ grids,
    const int* __restrict__ active_idx,
    const float* __restrict__ W_in, const float* __restrict__ b_in,
    const float* __restrict__ W_obs, const float* __restrict__ b_obs,
    const float* __restrict__ h_all, const float* __restrict__ c_all, int t)
{
    int wid = threadIdx.x >> 5, lane = threadIdx.x & 31;
    int k = blockIdx.x * 8 + wid;
    if (k >= K_ACT) return;
    int n = active_idx[t * K_ACT + k];
    if (lane == 0) atomicMax(&g_winner[n], t * K_ACT + k);

    // h gather -> A cols 128..255 (fp16); c gather -> dense scratch
    float4 h4 = *(const float4*)&h_all[(size_t)n * RNN + lane * 4];
    int jh = 128 + lane * 4;
    writeA2(k, jh + 0, __floats2half2_rn(h4.x, h4.y));
    writeA2(k, jh + 2, __floats2half2_rn(h4.z, h4.w));
    float4 c4 = *(const float4*)&c_all[(size_t)n * RNN + lane * 4];
    *(float4*)&g_cg[(size_t)k * RNN + lane * 4] = c4;

    // input embedding -> A cols 0..63 (this thread: cols 2*lane, 2*lane+1)
    float x0 = input_data[((size_t)t * N_NODES + n) * 2 + 0];
    float x1 = input_data[((size_t)t * N_NODES + n) * 2 + 1];
    {
        int j = 2 * lane;
        float v0 = fmaf(x0, W_in[j],     fmaf(x1, W_in[64 + j],     b_in[j]));
        float v1 = fmaf(x0, W_in[j + 1], fmaf(x1, W_in[64 + j + 1], b_in[j + 1]));
        writeA2(k, j, __floats2half2_rn(fmaxf(v0, 0.f), fmaxf(v1, 0.f)));
    }
    // grid embedding -> A cols 64..127
    const float* gp = grids + ((size_t)t * K_ACT + k) * 16;
    float obs[16];
    #pragma unroll
    for (int g = 0; g < 16; g++) obs[g] = gp[g];
    {
        int j = 2 * lane;
        float a0 = b_obs[j], a1 = b_obs[j + 1];
        #pragma unroll
        for (int g = 0; g < 16; g++) {
            a0 = fmaf(obs[g], W_obs[g * 64 + j],     a0);
            a1 = fmaf(obs[g], W_obs[g * 64 + j + 1], a1);
        }
        writeA2(k, 64 + j, __floats2half2_rn(fmaxf(a0, 0.f), fmaxf(a1, 0.f)));
    }
}

// ======================= per-frame: double-buffered smem fp16 GEMM + coalesced LSTM epilogue =======================
// grid (79, 4), 256 threads, 64KB dyn smem -> 2 CTAs/SM. Block tile 128m x 128n.
// Mainloop identical to R13 (proven). Epilogue rebuilt: gates staged in smem
// (STS.128), then a coalesced pass reads c-gather / writes h,c as float4 runs.
#define STAGE_BYTES 32768     // A 16KB + B 16KB
#define SG_STRIDE   132       // floats per gate-row (32 units * 4 gates + 4 pad); 132*4 % 16 == 0

__device__ __forceinline__ void load_chunk(uint32_t sa, uint32_t sb, int bx, int ny, int ch, int tid)
{
    const char* gA = (const char*)(g_Afrag + (size_t)bx * 8 * K16 * 32);
    const char* gB = (const char*)(g_Bfrag + (size_t)ny * 16 * K16 * 32);
    #pragma unroll
    for (int i = 0; i < 4; i++) {           // A: 1024 16B units
        int idx = tid + i * 256;
        int mg = idx >> 7, rem = idx & 127;
        int kk = rem >> 5, ln = rem & 31;
        uint32_t dst = sa + (uint32_t)(((mg * 4 + kk) * 32 + ln) * 16);
        uint32_t src = (uint32_t)(((mg * K16 + ch * 4 + kk) * 32 + ln) * 16);
        CPA16(dst, gA + src);
    }
    #pragma unroll
    for (int i = 0; i < 4; i++) {           // B: 1024 16B units
        int idx = tid + i * 256;
        int nf = idx >> 6, rem = idx & 63;
        int kk = rem >> 4, u = rem & 15;
        uint32_t dst = sb + (uint32_t)(((nf * 4 + kk) * 32) * 8 + u * 16);
        uint32_t src = (uint32_t)(((nf * K16 + ch * 4 + kk) * 32) * 8 + u * 16);
        CPA16(dst, gB + src);
    }
    asm volatile("cp.async.commit_group;" ::: "memory");
}

__global__ __launch_bounds__(256, 2) void gemm_kernel()
{
    extern __shared__ char sm[];
    const int tid = threadIdx.x, wid = tid >> 5, lane = tid & 31;
    const int wm = wid & 3, wn = wid >> 2;
    const int bx = blockIdx.x, ny = blockIdx.y;
    const int g = lane >> 2, tg = lane & 3;

    const uint32_t sbase = smem_u32(sm);

    // prologue: chunks 0,1 into stages 0,1
    load_chunk(sbase,               sbase + 16384,               bx, ny, 0, tid);
    load_chunk(sbase + STAGE_BYTES, sbase + STAGE_BYTES + 16384, bx, ny, 1, tid);

    float c[2][8][4];
    #pragma unroll
    for (int f = 0; f < 2; f++)
        #pragma unroll
        for (int j = 0; j < 8; j++)
            { c[f][j][0] = 0.f; c[f][j][1] = 0.f; c[f][j][2] = 0.f; c[f][j][3] = 0.f; }

    #pragma unroll
    for (int ch = 0; ch < 4; ch++) {
        if (ch < 3) asm volatile("cp.async.wait_group 1;" ::: "memory");
        else        asm volatile("cp.async.wait_group 0;" ::: "memory");
        __syncthreads();

        const int s = ch & 1;
        const uint4* A0 = (const uint4*)(sm + s * STAGE_BYTES) + (wm * 2 + 0) * 4 * 32 + lane;
        const uint4* A1 = (const uint4*)(sm + s * STAGE_BYTES) + (wm * 2 + 1) * 4 * 32 + lane;
        const uint2* Bq = (const uint2*)(sm + s * STAGE_BYTES + 16384) + (wn * 8) * 4 * 32 + lane;

        #pragma unroll
        for (int kk = 0; kk < 4; kk++) {
            uint4 a0 = A0[kk * 32];
            uint4 a1 = A1[kk * 32];
            uint2 bf[8];
            #pragma unroll
            for (int j = 0; j < 8; j++) bf[j] = Bq[(j * 4 + kk) * 32];
            #pragma unroll
            for (int j = 0; j < 8; j++) {
                MMA_F16(c[0][j], a0, bf[j]);
                MMA_F16(c[1][j], a1, bf[j]);
            }
        }

        if (ch < 2) {   // refill the stage just consumed with chunk ch+2
            __syncthreads();
            load_chunk(sbase + s * STAGE_BYTES, sbase + s * STAGE_BYTES + 16384, bx, ny, ch + 2, tid);
        }
    }
    __syncthreads();   // all warps past stage reads; smem free for gate staging

    // ---- LSTM epilogue: two passes of 64 rows; gates staged in smem, then
    // coalesced cg-gather + h/c writeback (float4 runs). ----
    float* sg = (float*)sm;    // [64 srow][SG_STRIDE] floats = 33.8KB
    #pragma unroll
    for (int f = 0; f < 2; f++) {
        // pass A: shuffle gate quads into smem
        #pragma unroll
        for (int j = 0; j < 8; j++) {
            float x0 = __shfl_xor_sync(0xffffffffu, c[f][j][0], 1);
            float x1 = __shfl_xor_sync(0xffffffffu, c[f][j][1], 1);
            float x2 = __shfl_xor_sync(0xffffffffu, c[f][j][2], 1);
            float x3 = __shfl_xor_sync(0xffffffffu, c[f][j][3], 1);
            int odd = lane & 1;
            float gi = odd ? x2 : c[f][j][0];
            float gf = odd ? x3 : c[f][j][1];
            float gg = odd ? c[f][j][2] : x0;
            float go = odd ? c[f][j][3] : x1;
            int srow = wm * 16 + g + odd * 8;                 // 0..63
            int ul   = (wn * 8 + j) * 2 + (tg >> 1);          // 0..31
            *(float4*)&sg[srow * SG_STRIDE + ul * 4] = make_float4(gi, gf, gg, go);
        }
        __syncthreads();
        // pass B: coalesced finish
        #pragma unroll
        for (int rr = 0; rr < 2; rr++) {
            int srow = rr * 32 + (tid >> 3);
            int q = tid & 7;
            int grow = bx * 128 + (srow >> 4) * 32 + f * 16 + (srow & 15);
            if (grow < K_ACT) {
                int u0 = ny * 32 + q * 4;
                float4 cg4 = *(const float4*)&g_cg[(size_t)grow * RNN + u0];
                float co[4] = {cg4.x, cg4.y, cg4.z, cg4.w};
                float hv[4], cv[4];
                #pragma unroll
                for (int e = 0; e < 4; e++) {
                    float4 gt = *(float4*)&sg[srow * SG_STRIDE + (q * 4 + e) * 4];
                    float4 br = g_br[u0 + e];
                    float ii = sigf(gt.x + br.x);
                    float ff = sigf(gt.y + br.y);
                    float G  = tanhfa(gt.z + br.z);
                    float oo = sigf(gt.w + br.w);
                    float cn = fmaf(ff, co[e], ii * G);
                    hv[e] = oo * tanhfa(cn);
                    cv[e] = cn;
                }
                *(float4*)&g_hs[(size_t)grow * RNN + u0] = make_float4(hv[0], hv[1], hv[2], hv[3]);
                *(float4*)&g_cs[(size_t)grow * RNN + u0] = make_float4(cv[0], cv[1], cv[2], cv[3]);
            }
        }
        if (f == 0) __syncthreads();   // protect sg before pass f=1 overwrites
    }
}

// ======================= per-frame: winner scatter + output projection =======================
__global__ __launch_bounds__(256) void scatter_kernel(
    const int* __restrict__ active_idx,
    const float* __restrict__ W_out, const float* __restrict__ b_out,
    float* __restrict__ outputs, float* __restrict__ h_all, float* __restrict__ c_all, int t)
{
    int lane = threadIdx.x & 31;
    int k = blockIdx.x * 8 + (threadIdx.x >> 5);
    if (k >= K_ACT) return;
    int n = active_idx[t * K_ACT + k];
    if (g_winner[n] != t * K_ACT + k) return;   // last-occurrence wins

    float4 h4 = *(float4*)&g_hs[(size_t)k * RNN + lane * 4];
    float4 c4 = *(float4*)&g_cs[(size_t)k * RNN + lane * 4];
    *(float4*)&h_all[(size_t)n * RNN + lane * 4] = h4;
    *(float4*)&c_all[(size_t)n * RNN + lane * 4] = c4;

    float p[OUT_SZ];
    int i0 = lane * 4;
    #pragma unroll
    for (int j = 0; j < OUT_SZ; j++) {
        p[j] = h4.x * W_out[(i0 + 0) * OUT_SZ + j]
             + h4.y * W_out[(i0 + 1) * OUT_SZ + j]
             + h4.z * W_out[(i0 + 2) * OUT_SZ + j]
             + h4.w * W_out[(i0 + 3) * OUT_SZ + j];
    }
    #pragma unroll
    for (int off = 16; off > 0; off >>= 1) {
        #pragma unroll
        for (int j = 0; j < OUT_SZ; j++)
            p[j] += __shfl_down_sync(0xffffffffu, p[j], off);
    }
    if (lane == 0) {
        #pragma unroll
        for (int j = 0; j < OUT_SZ; j++)
            outputs[((size_t)t * N_NODES + n) * OUT_SZ + j] = p[j] + b_out[j];
    }
}

// ======================= launcher =======================
extern "C" void kernel_launch(void* const* d_in, const int* in_sizes, int n_in,
                              void* d_out, int out_size)
{
    const float* input_data = (const float*)d_in[0];
    const float* grids      = (const float*)d_in[1];
    const float* h0         = (const float*)d_in[2];
    const float* c0         = (const float*)d_in[3];
    const int*   active_idx = (const int*)  d_in[4];
    const float* W_in       = (const float*)d_in[5];
    const float* b_in       = (const float*)d_in[6];
    const float* W_obs      = (const float*)d_in[7];
    const float* b_obs      = (const float*)d_in[8];
    const float* W_ih       = (const float*)d_in[9];
    const float* b_ih       = (const float*)d_in[10];
    const float* W_hh       = (const float*)d_in[11];
    const float* b_hh       = (const float*)d_in[12];
    const float* W_out      = (const float*)d_in[13];
    const float* b_out      = (const float*)d_in[14];

    float* out     = (float*)d_out;
    float* outputs = out;
    float* h_all   = out + (size_t)T_STEPS * N_NODES * OUT_SZ;
    float* c_all   = h_all + (size_t)N_NODES * RNN;

    const int SMEM = 2 * STAGE_BYTES;   // 64KB
    cudaFuncSetAttribute(gemm_kernel, cudaFuncAttributeMaxDynamicSharedMemorySize, SMEM);

    init_weights_kernel<<<512, 256>>>(W_ih, b_ih, W_hh, b_hh);
    init_state_kernel<<<1024, 256>>>(out, h0, c0);

    for (int t = 0; t < T_STEPS; t++) {
        embed_kernel<<<(K_ACT + 7) / 8, 256>>>(input_data, grids, active_idx,
                                               W_in, b_in, W_obs, b_obs, h_all, c_all, t);
        gemm_kernel<<<dim3(M_TILES, 4), 256, SMEM>>>();
        scatter_kernel<<<(K_ACT + 7) / 8, 256>>>(active_idx, W_out, b_out,
                                                 outputs, h_all, c_all, t);
    }
}

// round 17
// speedup vs baseline: 1.2397x; 1.0918x over previous
#include <cuda_runtime.h>
#include <cuda_fp16.h>
#include <cstdint>
#include <cstring>

#define T_STEPS 20
#define N_NODES 50000
#define K_ACT   10000
#define RNN     128
#define OUT_SZ  5
#define M_TILES 79
#define MG_CNT  (M_TILES * 8)     // 632 groups of 16 rows
#define K16     16                // 256 / 16

// -------- device scratch (static; no allocation) --------
__device__ uint4 g_Afrag[(size_t)MG_CNT * K16 * 32];   // A fp16 fragments
__device__ uint2 g_Bfrag[64 * K16 * 32];               // B fp16 fragments
__device__ float4 g_br[RNN];                   // per-unit (bi,bf,bg,bo)
__device__ int    g_winner[N_NODES];           // last-wins stamps

// ======================= helpers =======================
__device__ __forceinline__ float sigf(float x)   { return __fdividef(1.f, 1.f + __expf(-x)); }
__device__ __forceinline__ float tanhfa(float x) { return __fdividef(2.f, 1.f + __expf(-2.f * x)) - 1.f; }

__device__ __forceinline__ uint32_t h2u(__half2 v) {
    uint32_t u;
    memcpy(&u, &v, 4);
    return u;
}
__device__ __forceinline__ uint32_t smem_u32(const void* p) {
    uint32_t a;
    asm("{ .reg .u64 t; cvta.to.shared.u64 t, %1; cvt.u32.u64 %0, t; }" : "=r"(a) : "l"(p));
    return a;
}
#define CPA16(s, g) asm volatile("cp.async.cg.shared.global [%0], [%1], 16;" :: "r"(s), "l"(g))

// Write an even-aligned (col j, j+1) half2 pair of A in fragment layout.
__device__ __forceinline__ void writeA2(int m, int j, __half2 v) {
    int mg = m >> 4, r = m & 15;
    int k16 = j >> 4, kk = j & 15;                 // kk even
    int lane = (r & 7) * 4 + ((kk & 7) >> 1);
    int reg  = ((kk >> 3) << 1) | (r >> 3);
    ((uint32_t*)g_Afrag)[((((size_t)mg * K16 + k16) * 32) + lane) * 4 + reg] = h2u(v);
}

#define MMA_F16(cc, aa, bb) \
    asm volatile("mma.sync.aligned.m16n8k16.row.col.f32.f16.f16.f32 " \
        "{%0,%1,%2,%3},{%4,%5,%6,%7},{%8,%9},{%0,%1,%2,%3};" \
        : "+f"((cc)[0]), "+f"((cc)[1]), "+f"((cc)[2]), "+f"((cc)[3]) \
        : "r"((aa).x), "r"((aa).y), "r"((aa).z), "r"((aa).w), \
          "r"((bb).x), "r"((bb).y))

// ======================= init kernels =======================
__global__ void init_weights_kernel(const float* __restrict__ W_ih, const float* __restrict__ b_ih,
                                    const float* __restrict__ W_hh, const float* __restrict__ b_hh)
{
    int cp = blockIdx.x;     // rearranged column col' = unit*4+gate, 0..511
    int r  = threadIdx.x;    // inner k, 0..255
    int unit = cp >> 2, gate = cp & 3;
    int col = gate * RNN + unit;
    float v = (r < RNN) ? W_ih[r * 512 + col] : W_hh[(r - RNN) * 512 + col];
    int nf = cp >> 3;
    int lane = (cp & 7) * 4 + ((r & 7) >> 1);
    int reg = (r >> 3) & 1, halfpos = r & 1, k16 = r >> 4;
    ((__half*)g_Bfrag)[((((size_t)nf * K16 + k16) * 32 + lane) * 2 + reg) * 2 + halfpos] = __float2half_rn(v);
    if (r == 0) ((float*)g_br)[cp] = b_ih[col] + b_hh[col];
}

__global__ void init_state_kernel(float* __restrict__ out,
                                  const float* __restrict__ h0, const float* __restrict__ c0)
{
    const int OUT_TOTAL = T_STEPS * N_NODES * OUT_SZ;
    const int HOFF = OUT_TOTAL;
    const int COFF = HOFF + N_NODES * RNN;
    const int WOFF = COFF + N_NODES * RNN;
    const int TOTAL = WOFF + N_NODES;
    for (int i = blockIdx.x * blockDim.x + threadIdx.x; i < TOTAL; i += gridDim.x * blockDim.x) {
        if (i < OUT_TOTAL)      out[i] = 0.f;
        else if (i < COFF)      out[i] = h0[i - HOFF];
        else if (i < WOFF)      out[i] = c0[i - COFF];
        else                    g_winner[i - WOFF] = -1;
    }
}

// ======================= per-frame: embed + stamp =======================
__global__ __launch_bounds__(256) void embed_kernel(
    const float* __restrict__ input_data, const float* __restrict__ grids,
    const int* __restrict__ active_idx,
    const float* __restrict__ W_in, const float* __restrict__ b_in,
    const float* __restrict__ W_obs, const float* __restrict__ b_obs,
    const float* __restrict__ h_all, int t)
{
    int wid = threadIdx.x >> 5, lane = threadIdx.x & 31;
    int k = blockIdx.x * 8 + wid;
    if (k >= K_ACT) return;
    int n = active_idx[t * K_ACT + k];
    if (lane == 0) atomicMax(&g_winner[n], t * K_ACT + k);

    // h gather -> A cols 128..255 (fp16)
    float4 h4 = *(const float4*)&h_all[(size_t)n * RNN + lane * 4];
    int jh = 128 + lane * 4;
    writeA2(k, jh + 0, __floats2half2_rn(h4.x, h4.y));
    writeA2(k, jh + 2, __floats2half2_rn(h4.z, h4.w));

    // input embedding -> A cols 0..63 (this thread: cols 2*lane, 2*lane+1)
    float x0 = input_data[((size_t)t * N_NODES + n) * 2 + 0];
    float x1 = input_data[((size_t)t * N_NODES + n) * 2 + 1];
    {
        int j = 2 * lane;
        float v0 = fmaf(x0, W_in[j],     fmaf(x1, W_in[64 + j],     b_in[j]));
        float v1 = fmaf(x0, W_in[j + 1], fmaf(x1, W_in[64 + j + 1], b_in[j + 1]));
        writeA2(k, j, __floats2half2_rn(fmaxf(v0, 0.f), fmaxf(v1, 0.f)));
    }
    // grid embedding -> A cols 64..127
    const float* gp = grids + ((size_t)t * K_ACT + k) * 16;
    float obs[16];
    #pragma unroll
    for (int g = 0; g < 16; g++) obs[g] = gp[g];
    {
        int j = 2 * lane;
        float a0 = b_obs[j], a1 = b_obs[j + 1];
        #pragma unroll
        for (int g = 0; g < 16; g++) {
            a0 = fmaf(obs[g], W_obs[g * 64 + j],     a0);
            a1 = fmaf(obs[g], W_obs[g * 64 + j + 1], a1);
        }
        writeA2(k, 64 + j, __floats2half2_rn(fmaxf(a0, 0.f), fmaxf(a1, 0.f)));
    }
}

// ======================= per-frame: fp16 GEMM + LSTM + winner state writeback + projection =======================
// grid (79, 4), 256 threads, 64KB dyn smem -> 2 CTAs/SM. Block tile 128m x 128n.
// Mainloop identical to R13/R16 (proven). Epilogue: gates staged in smem, then a
// coalesced pass computes the LSTM pointwise for WINNER rows only, writes h/c
// straight into the live state (disjoint 32-unit slice per ny, unique winner per
// node -> race free), and accumulates the 5-wide output projection via atomicAdd.
#define STAGE_BYTES 32768     // A 16KB + B 16KB
#define SG_STRIDE   132       // floats per gate-row (32 units * 4 gates + 4 pad)

__device__ __forceinline__ void load_chunk(uint32_t sa, uint32_t sb, int bx, int ny, int ch, int tid)
{
    const char* gA = (const char*)(g_Afrag + (size_t)bx * 8 * K16 * 32);
    const char* gB = (const char*)(g_Bfrag + (size_t)ny * 16 * K16 * 32);
    #pragma unroll
    for (int i = 0; i < 4; i++) {           // A: 1024 16B units
        int idx = tid + i * 256;
        int mg = idx >> 7, rem = idx & 127;
        int kk = rem >> 5, ln = rem & 31;
        uint32_t dst = sa + (uint32_t)(((mg * 4 + kk) * 32 + ln) * 16);
        uint32_t src = (uint32_t)(((mg * K16 + ch * 4 + kk) * 32 + ln) * 16);
        CPA16(dst, gA + src);
    }
    #pragma unroll
    for (int i = 0; i < 4; i++) {           // B: 1024 16B units
        int idx = tid + i * 256;
        int nf = idx >> 6, rem = idx & 63;
        int kk = rem >> 4, u = rem & 15;
        uint32_t dst = sb + (uint32_t)(((nf * 4 + kk) * 32) * 8 + u * 16);
        uint32_t src = (uint32_t)(((nf * K16 + ch * 4 + kk) * 32) * 8 + u * 16);
        CPA16(dst, gB + src);
    }
    asm volatile("cp.async.commit_group;" ::: "memory");
}

__global__ __launch_bounds__(256, 2) void gemm_kernel(
    const int* __restrict__ active_idx,
    const float* __restrict__ W_out, const float* __restrict__ b_out,
    float* __restrict__ outputs, float* __restrict__ h_all, float* __restrict__ c_all, int t)
{
    extern __shared__ char sm[];
    const int tid = threadIdx.x, wid = tid >> 5, lane = tid & 31;
    const int wm = wid & 3, wn = wid >> 2;
    const int bx = blockIdx.x, ny = blockIdx.y;
    const int g = lane >> 2, tg = lane & 3;

    const uint32_t sbase = smem_u32(sm);

    // prologue: chunks 0,1 into stages 0,1
    load_chunk(sbase,               sbase + 16384,               bx, ny, 0, tid);
    load_chunk(sbase + STAGE_BYTES, sbase + STAGE_BYTES + 16384, bx, ny, 1, tid);

    float c[2][8][4];
    #pragma unroll
    for (int f = 0; f < 2; f++)
        #pragma unroll
        for (int j = 0; j < 8; j++)
            { c[f][j][0] = 0.f; c[f][j][1] = 0.f; c[f][j][2] = 0.f; c[f][j][3] = 0.f; }

    #pragma unroll
    for (int ch = 0; ch < 4; ch++) {
        if (ch < 3) asm volatile("cp.async.wait_group 1;" ::: "memory");
        else        asm volatile("cp.async.wait_group 0;" ::: "memory");
        __syncthreads();

        const int s = ch & 1;
        const uint4* A0 = (const uint4*)(sm + s * STAGE_BYTES) + (wm * 2 + 0) * 4 * 32 + lane;
        const uint4* A1 = (const uint4*)(sm + s * STAGE_BYTES) + (wm * 2 + 1) * 4 * 32 + lane;
        const uint2* Bq = (const uint2*)(sm + s * STAGE_BYTES + 16384) + (wn * 8) * 4 * 32 + lane;

        #pragma unroll
        for (int kk = 0; kk < 4; kk++) {
            uint4 a0 = A0[kk * 32];
            uint4 a1 = A1[kk * 32];
            uint2 bf[8];
            #pragma unroll
            for (int j = 0; j < 8; j++) bf[j] = Bq[(j * 4 + kk) * 32];
            #pragma unroll
            for (int j = 0; j < 8; j++) {
                MMA_F16(c[0][j], a0, bf[j]);
                MMA_F16(c[1][j], a1, bf[j]);
            }
        }

        if (ch < 2) {   // refill the stage just consumed with chunk ch+2
            __syncthreads();
            load_chunk(sbase + s * STAGE_BYTES, sbase + s * STAGE_BYTES + 16384, bx, ny, ch + 2, tid);
        }
    }
    __syncthreads();   // all warps past stage reads; smem free for gate staging

    // ---- epilogue: two passes of 64 rows ----
    float* sg = (float*)sm;    // [64 srow][SG_STRIDE] floats
    #pragma unroll
    for (int f = 0; f < 2; f++) {
        // pass A: shuffle gate quads into smem
        #pragma unroll
        for (int j = 0; j < 8; j++) {
            float x0 = __shfl_xor_sync(0xffffffffu, c[f][j][0], 1);
            float x1 = __shfl_xor_sync(0xffffffffu, c[f][j][1], 1);
            float x2 = __shfl_xor_sync(0xffffffffu, c[f][j][2], 1);
            float x3 = __shfl_xor_sync(0xffffffffu, c[f][j][3], 1);
            int odd = lane & 1;
            float gi = odd ? x2 : c[f][j][0];
            float gf = odd ? x3 : c[f][j][1];
            float gg = odd ? c[f][j][2] : x0;
            float go = odd ? c[f][j][3] : x1;
            int srow = wm * 16 + g + odd * 8;                 // 0..63
            int ul   = (wn * 8 + j) * 2 + (tg >> 1);          // 0..31
            *(float4*)&sg[srow * SG_STRIDE + ul * 4] = make_float4(gi, gf, gg, go);
        }
        __syncthreads();
        // pass B: winner rows only — LSTM pointwise, state writeback, projection
        #pragma unroll
        for (int rr = 0; rr < 2; rr++) {
            int srow = rr * 32 + (tid >> 3);
            int q = tid & 7;
            int grow = bx * 128 + (srow >> 4) * 32 + f * 16 + (srow & 15);
            float p[OUT_SZ] = {0.f, 0.f, 0.f, 0.f, 0.f};
            int n = -1;
            bool win = false;
            if (grow < K_ACT) {
                n = active_idx[t * K_ACT + grow];              // broadcast within oct
                win = (g_winner[n] == t * K_ACT + grow);
            }
            if (win) {
                int u0 = ny * 32 + q * 4;
                float4 cg4 = *(const float4*)&c_all[(size_t)n * RNN + u0];
                float co[4] = {cg4.x, cg4.y, cg4.z, cg4.w};
                float hv[4], cv[4];
                #pragma unroll
                for (int e = 0; e < 4; e++) {
                    float4 gt = *(float4*)&sg[srow * SG_STRIDE + (q * 4 + e) * 4];
                    float4 br = g_br[u0 + e];
                    float ii = sigf(gt.x + br.x);
                    float ff = sigf(gt.y + br.y);
                    float G  = tanhfa(gt.z + br.z);
                    float oo = sigf(gt.w + br.w);
                    float cn = fmaf(ff, co[e], ii * G);
                    hv[e] = oo * tanhfa(cn);
                    cv[e] = cn;
                }
                *(float4*)&h_all[(size_t)n * RNN + u0] = make_float4(hv[0], hv[1], hv[2], hv[3]);
                *(float4*)&c_all[(size_t)n * RNN + u0] = make_float4(cv[0], cv[1], cv[2], cv[3]);
                #pragma unroll
                for (int j = 0; j < OUT_SZ; j++) {
                    p[j] = hv[0] * W_out[(u0 + 0) * OUT_SZ + j]
                         + hv[1] * W_out[(u0 + 1) * OUT_SZ + j]
                         + hv[2] * W_out[(u0 + 2) * OUT_SZ + j]
                         + hv[3] * W_out[(u0 + 3) * OUT_SZ + j];
                }
            }
            // reduce the 8 q-lanes (width=8 keeps octs independent)
            #pragma unroll
            for (int off = 4; off > 0; off >>= 1) {
                #pragma unroll
                for (int j = 0; j < OUT_SZ; j++)
                    p[j] += __shfl_down_sync(0xffffffffu, p[j], off, 8);
            }
            if (win && q == 0) {
                float* op = &outputs[((size_t)t * N_NODES + n) * OUT_SZ];
                #pragma unroll
                for (int j = 0; j < OUT_SZ; j++) {
                    float add = p[j] + (ny == 0 ? b_out[j] : 0.f);
                    atomicAdd(&op[j], add);
                }
            }
        }
        if (f == 0) __syncthreads();   // protect sg before pass f=1 overwrites
    }
}

// ======================= launcher =======================
extern "C" void kernel_launch(void* const* d_in, const int* in_sizes, int n_in,
                              void* d_out, int out_size)
{
    const float* input_data = (const float*)d_in[0];
    const float* grids      = (const float*)d_in[1];
    const float* h0         = (const float*)d_in[2];
    const float* c0         = (const float*)d_in[3];
    const int*   active_idx = (const int*)  d_in[4];
    const float* W_in       = (const float*)d_in[5];
    const float* b_in       = (const float*)d_in[6];
    const float* W_obs      = (const float*)d_in[7];
    const float* b_obs      = (const float*)d_in[8];
    const float* W_ih       = (const float*)d_in[9];
    const float* b_ih       = (const float*)d_in[10];
    const float* W_hh       = (const float*)d_in[11];
    const float* b_hh       = (const float*)d_in[12];
    const float* W_out      = (const float*)d_in[13];
    const float* b_out      = (const float*)d_in[14];

    float* out     = (float*)d_out;
    float* outputs = out;
    float* h_all   = out + (size_t)T_STEPS * N_NODES * OUT_SZ;
    float* c_all   = h_all + (size_t)N_NODES * RNN;

    const int SMEM = 2 * STAGE_BYTES;   // 64KB
    cudaFuncSetAttribute(gemm_kernel, cudaFuncAttributeMaxDynamicSharedMemorySize, SMEM);

    init_weights_kernel<<<512, 256>>>(W_ih, b_ih, W_hh, b_hh);
    init_state_kernel<<<1024, 256>>>(out, h0, c0);

    for (int t = 0; t < T_STEPS; t++) {
        embed_kernel<<<(K_ACT + 7) / 8, 256>>>(input_data, grids, active_idx,
                                               W_in, b_in, W_obs, b_obs, h_all, t);
        gemm_kernel<<<dim3(M_TILES, 4), 256, SMEM>>>(active_idx, W_out, b_out,
                                                     outputs, h_all, c_all, t);
    }
}